// round 5
// baseline (speedup 1.0000x reference)
#include <cuda_runtime.h>

// ---------------- scratch (no allocations allowed) ----------------
#define MAX_K      65536
#define MAX_BLOCKS 4096
#define CBS        256   // compaction block size

__device__ int g_idx[MAX_K];        // compacted masked node ids, in node order
__device__ int g_counts[MAX_BLOCKS];

// ---------------- pass 1: per-block masked count ----------------
__global__ void count_kernel(const int* __restrict__ sym, int N,
                             const int* __restrict__ symbuf, int T) {
    __shared__ int sbuf[8];
    __shared__ int warp_cnt[CBS / 32];
    int tid = threadIdx.x;
    if (tid < T && tid < 8) sbuf[tid] = symbuf[tid];
    __syncthreads();
    int i = blockIdx.x * CBS + tid;
    bool m = false;
    if (i < N) {
        int s = sym[i];
        #pragma unroll 4
        for (int t = 0; t < T; t++) m |= (s == sbuf[t]);
    }
    unsigned ball = __ballot_sync(0xffffffffu, m);
    if ((tid & 31) == 0) warp_cnt[tid >> 5] = __popc(ball);
    __syncthreads();
    if (tid == 0) {
        int c = 0;
        #pragma unroll
        for (int k = 0; k < CBS / 32; k++) c += warp_cnt[k];
        g_counts[blockIdx.x] = c;
    }
}

// ---------------- pass 2 (fused): per-block prefix recompute + ordered scatter ----------------
__global__ void scatter_fused_kernel(const int* __restrict__ sym, int N,
                                     const int* __restrict__ symbuf, int T) {
    __shared__ int sbuf[8];
    __shared__ int red[CBS / 32];
    __shared__ int warp_off[CBS / 32];
    __shared__ int block_pre;

    int tid = threadIdx.x;
    int b = blockIdx.x;
    if (tid < T && tid < 8) sbuf[tid] = symbuf[tid];

    // exclusive prefix for this block: sum g_counts[0..b)
    int pre = 0;
    for (int j = tid; j < b; j += CBS) pre += g_counts[j];
    #pragma unroll
    for (int o = 16; o; o >>= 1) pre += __shfl_down_sync(0xffffffffu, pre, o);
    if ((tid & 31) == 0) red[tid >> 5] = pre;
    __syncthreads();
    if (tid == 0) {
        int s = 0;
        #pragma unroll
        for (int k = 0; k < CBS / 32; k++) s += red[k];
        block_pre = s;
    }
    __syncthreads();

    // recompute mask + intra-block rank, scatter
    int i = b * CBS + tid;
    bool m = false;
    if (i < N) {
        int s = sym[i];
        #pragma unroll 4
        for (int t = 0; t < T; t++) m |= (s == sbuf[t]);
    }
    unsigned ball = __ballot_sync(0xffffffffu, m);
    int lane = tid & 31, w = tid >> 5;
    if (lane == 0) warp_off[w] = __popc(ball);
    __syncthreads();
    if (tid == 0) {
        int acc = 0;
        #pragma unroll
        for (int k = 0; k < CBS / 32; k++) { int c = warp_off[k]; warp_off[k] = acc; acc += c; }
    }
    __syncthreads();
    if (m) {
        int pos = block_pre + warp_off[w] + __popc(ball & ((1u << lane) - 1u));
        g_idx[pos] = i;
    }
}

// ---------------- main: warp-per-masked-node gather-dot (at BW roofline; unchanged) ----------------
__device__ __forceinline__ float dot4(float4 a, float4 b) {
    return a.x * b.x + a.y * b.y + a.z * b.z + a.w * b.w;
}

__global__ void __launch_bounds__(256, 8) gatherdot_kernel(
    const float* __restrict__ f00, const float* __restrict__ f01,
    const float* __restrict__ f10, const float* __restrict__ f11,
    const float* __restrict__ f20, const float* __restrict__ f21,
    const float* __restrict__ w0, const float* __restrict__ w1,
    const float* __restrict__ w2,
    const float* __restrict__ b0, const float* __restrict__ b1,
    const float* __restrict__ b2,
    const int* __restrict__ meta,
    float* __restrict__ out, int K, int d4)
{
    int gw = (blockIdx.x * blockDim.x + threadIdx.x) >> 5;
    if (gw >= K) return;
    int lane = threadIdx.x & 31;

    int i = g_idx[gw];
    int mid = meta[i];

    size_t fo = (size_t)i * (size_t)d4;
    size_t wo = (size_t)mid * (size_t)d4;

    // independent bias loads issued early (L2-resident, tiny)
    float bias = 2.0f * (b0[mid] + b1[mid] + b2[mid]);

    float acc = 0.0f;

    #pragma unroll 3
    for (int p = 0; p < 3; p++) {
        const float4* W;
        const float4* Fa;
        const float4* Fb;
        if (p == 0)      { W = (const float4*)w0; Fa = (const float4*)f00; Fb = (const float4*)f01; }
        else if (p == 1) { W = (const float4*)w1; Fa = (const float4*)f10; Fb = (const float4*)f11; }
        else             { W = (const float4*)w2; Fa = (const float4*)f20; Fb = (const float4*)f21; }

        #pragma unroll 2
        for (int c = lane; c < d4; c += 32) {
            float4 a  = W[wo + c];               // L2-cached (heavy reuse across nodes)
            float4 x0 = __ldcs(&Fa[fo + c]);     // streamed, no reuse
            float4 x1 = __ldcs(&Fb[fo + c]);
            acc += dot4(x0, a) + dot4(x1, a);
        }
    }

    // warp reduction
    #pragma unroll
    for (int off = 16; off; off >>= 1)
        acc += __shfl_down_sync(0xffffffffu, acc, off);

    if (lane == 0) {
        out[gw] = (acc + bias) * (1.0f / 6.0f);
    }
}

// ---------------- launcher ----------------
extern "C" void kernel_launch(void* const* d_in, const int* in_sizes, int n_in,
                              void* d_out, int out_size) {
    const float* f00 = (const float*)d_in[0];
    const float* f01 = (const float*)d_in[1];
    const float* f10 = (const float*)d_in[2];
    const float* f11 = (const float*)d_in[3];
    const float* f20 = (const float*)d_in[4];
    const float* f21 = (const float*)d_in[5];
    const float* w0  = (const float*)d_in[6];
    const float* w1  = (const float*)d_in[7];
    const float* w2  = (const float*)d_in[8];
    const float* b0  = (const float*)d_in[9];
    const float* b1  = (const float*)d_in[10];
    const float* b2  = (const float*)d_in[11];
    const int* symbols = (const int*)d_in[12];
    const int* meta    = (const int*)d_in[13];
    const int* sym_buf = (const int*)d_in[14];

    int M = in_sizes[9];                 // b0 has M elements
    int D = in_sizes[6] / M;             // w0 has M*D
    int N = in_sizes[0] / D;             // feat00 has N*D
    int T = in_sizes[14];                // sym_buf length
    int K = out_size;                    // masked count
    (void)M; (void)n_in;

    int nb = (N + CBS - 1) / CBS;        // 782 for N=200000 (< MAX_BLOCKS)

    count_kernel<<<nb, CBS>>>(symbols, N, sym_buf, T);
    scatter_fused_kernel<<<nb, CBS>>>(symbols, N, sym_buf, T);

    int warps_per_block = 8;             // 256 threads
    int blocks = (K + warps_per_block - 1) / warps_per_block;
    gatherdot_kernel<<<blocks, warps_per_block * 32>>>(
        f00, f01, f10, f11, f20, f21,
        w0, w1, w2, b0, b1, b2,
        meta, (float*)d_out, K, D / 4);
}